// round 16
// baseline (speedup 1.0000x reference)
#include <cuda_runtime.h>
#include <cstdint>

#define BB   16
#define CIN  32
#define COUT 32
#define HH   256
#define WW   256

// ---------------- scratch (device globals; no cudaMalloc) ----------------
__device__ float2 g_B1[32*32*4];                     // stage1 B frag pairs [kstep32][n32][c4]
__device__ float2 g_B5[4*256*4];                     // stage5 B frag pairs [kstep4][w256][c4]
__device__ float2 g_TW256[256];                      // e^{-2pi i a h0/256}, [a*16+h0]
__device__ float2 g_TW16[16];                        // e^{-2pi i t/16}
__device__ float2 g_wpack[512*32*32];                // [mode][i*32+o]
__device__ float2 g_Xft[512*512];                    // [mode][b*32+i]  (mode-major)
__device__ float2 g_Yft[BB*COUT*32*16];              // [b,o][kxidx][ky]

__device__ __forceinline__ float tf32rna(float x) {
    uint32_t u; asm("cvt.rna.tf32.f32 %0, %1;" : "=r"(u) : "f"(x));
    return __uint_as_float(u);
}
__device__ __forceinline__ uint32_t smem_u32(const void* p) {
    uint32_t a;
    asm("{ .reg .u64 t; cvta.to.shared.u64 t, %1; cvt.u32.u64 %0, t; }" : "=r"(a) : "l"(p));
    return a;
}
__device__ __forceinline__ float2 cadd(float2 a, float2 b) { return make_float2(a.x+b.x, a.y+b.y); }
__device__ __forceinline__ float2 csub(float2 a, float2 b) { return make_float2(a.x-b.x, a.y-b.y); }
__device__ __forceinline__ float2 cmul(float2 a, float2 b) {        // a*b
    return make_float2(a.x*b.x - a.y*b.y, a.x*b.y + a.y*b.x);
}
__device__ __forceinline__ float2 cmulc(float2 a, float2 b) {       // a*conj(b)
    return make_float2(a.x*b.x + a.y*b.y, a.y*b.x - a.x*b.y);
}
__device__ __forceinline__ float2 addi(float2 a, float2 b) { return make_float2(a.x - b.y, a.y + b.x); }  // a + i*b
__device__ __forceinline__ float2 subi(float2 a, float2 b) { return make_float2(a.x + b.y, a.y - b.x); }  // a - i*b

// 4x4 transpose across a quad (lanes lc=0..3): out v[j](lane lc) = in v[lc](lane j).
// Two butterfly stages with static register indices (verified by element trace).
__device__ __forceinline__ void quad_transpose(float2 v[4], int lc) {
    const unsigned m = 0xFFFFFFFFu;
    int b = (lc >> 1) & 1, a = lc & 1;
    {   // stage 1: exchange lane bit1 <-> slot bit1 (mask 2)
        float2 s0 = b ? v[0] : v[2];
        float2 s1 = b ? v[1] : v[3];
        float2 r0, r1;
        r0.x = __shfl_xor_sync(m, s0.x, 2); r0.y = __shfl_xor_sync(m, s0.y, 2);
        r1.x = __shfl_xor_sync(m, s1.x, 2); r1.y = __shfl_xor_sync(m, s1.y, 2);
        if (b) { v[0] = r0; v[1] = r1; } else { v[2] = r0; v[3] = r1; }
    }
    {   // stage 2: exchange lane bit0 <-> slot bit0 (mask 1)
        float2 s0 = a ? v[0] : v[1];
        float2 s1 = a ? v[2] : v[3];
        float2 r0, r1;
        r0.x = __shfl_xor_sync(m, s0.x, 1); r0.y = __shfl_xor_sync(m, s0.y, 1);
        r1.x = __shfl_xor_sync(m, s1.x, 1); r1.y = __shfl_xor_sync(m, s1.y, 1);
        if (a) { v[0] = r0; v[2] = r1; } else { v[1] = r0; v[3] = r1; }
    }
}

#define CP_ASYNC16(dst, src) asm volatile("cp.async.cg.shared.global [%0], [%1], 16;" :: "r"(dst), "l"(src))
#define CP_COMMIT()          asm volatile("cp.async.commit_group;" ::: "memory")
#define CP_WAIT(n)           asm volatile("cp.async.wait_group %0;" :: "n"(n) : "memory")

__device__ __forceinline__ void mma_tf32(float d[4], uint32_t a0, uint32_t a1, uint32_t a2, uint32_t a3,
                                         uint32_t b0, uint32_t b1) {
    asm volatile(
        "mma.sync.aligned.m16n8k8.row.col.f32.tf32.tf32.f32 "
        "{%0,%1,%2,%3}, {%4,%5,%6,%7}, {%8,%9}, {%0,%1,%2,%3};"
        : "+f"(d[0]), "+f"(d[1]), "+f"(d[2]), "+f"(d[3])
        : "r"(a0), "r"(a1), "r"(a2), "r"(a3), "r"(b0), "r"(b1));
}

// ---------------- prep: blocks 0..127 repack (smem transpose), 128..161 tables ----------------
__global__ void prep(const float* __restrict__ w1r, const float* __restrict__ w1i,
                     const float* __restrict__ w2r, const float* __restrict__ w2i) {
    __shared__ float sw[4][2048];    // 8 pairs x 256 modes, 4 arrays (32 KB)
    int blk = blockIdx.x, tid = threadIdx.x;
    if (blk < 128) {
        int p0 = blk * 8;
        const float* srcs[4] = {w1r, w1i, w2r, w2i};
        #pragma unroll
        for (int a = 0; a < 4; a++) {
            const float4* s4 = (const float4*)(srcs[a] + p0*256);
            float4* d4 = (float4*)sw[a];
            d4[tid]       = s4[tid];
            d4[tid + 256] = s4[tid + 256];
        }
        __syncthreads();
        int j = tid;
        float2 v1[8], v2[8];
        #pragma unroll
        for (int pl = 0; pl < 8; pl++) {
            v1[pl] = make_float2(sw[0][pl*256 + j], sw[1][pl*256 + j]);
            v2[pl] = make_float2(sw[2][pl*256 + j], sw[3][pl*256 + j]);
        }
        float4* o1 = (float4*)&g_wpack[(size_t)j*1024 + p0];
        float4* o2 = (float4*)&g_wpack[(size_t)(256 + j)*1024 + p0];
        #pragma unroll
        for (int q = 0; q < 4; q++) {
            o1[q] = make_float4(v1[2*q].x, v1[2*q].y, v1[2*q+1].x, v1[2*q+1].y);
            o2[q] = make_float4(v2[2*q].x, v2[2*q].y, v2[2*q+1].x, v2[2*q+1].y);
        }
        return;
    }
    int idx = (blk - 128) * 256 + tid;
    if (idx < 4096) {                        // g_B1[kstep][n][c]
        int c = idx & 3, n = (idx >> 2) & 31, kstep = idx >> 7;
        int ky = n >> 1;
        int k0 = kstep*8 + c, k1 = k0 + 4;
        int t0 = (ky * k0) & 255, t1 = (ky * k1) & 255;
        float s0, c0, s1, c1;
        sincospif(t0 * (1.0f/128.0f), &s0, &c0);
        sincospif(t1 * (1.0f/128.0f), &s1, &c1);
        float v0 = (n & 1) ? -s0 : c0;
        float v1 = (n & 1) ? -s1 : c1;
        g_B1[idx] = make_float2(tf32rna(v0), tf32rna(v1));
    } else if (idx < 8192) {                 // g_B5[kstep][w][c]
        int j = idx - 4096;
        int c = j & 3, w = (j >> 2) & 255, kstep = j >> 10;
        int k0 = kstep*8 + c, k1 = k0 + 4;
        int ky0 = k0 >> 1, ky1 = k1 >> 1;
        int t0 = (ky0 * w) & 255, t1 = (ky1 * w) & 255;
        float s0, c0, s1, c1;
        sincospif(t0 * (1.0f/128.0f), &s0, &c0);
        sincospif(t1 * (1.0f/128.0f), &s1, &c1);
        float cf0 = ((ky0 == 0) ? 1.0f : 2.0f) * (1.0f/65536.0f);
        float cf1 = ((ky1 == 0) ? 1.0f : 2.0f) * (1.0f/65536.0f);
        float v0 = (k0 & 1) ? -cf0 * s0 : cf0 * c0;
        float v1 = (k1 & 1) ? -cf1 * s1 : cf1 * c1;
        g_B5[j] = make_float2(tf32rna(v0), tf32rna(v1));
    } else if (idx < 8448) {                 // g_TW256[a*16+h0]
        int j = idx - 8192;
        int a = j >> 4, h0 = j & 15;
        int t = (a * h0) & 255;
        float s, c; sincospif(t * (1.0f/128.0f), &s, &c);
        g_TW256[j] = make_float2(c, -s);
    } else if (idx < 8464) {                 // g_TW16[t]
        int t = idx - 8448;
        float s, c; sincospif(t * (1.0f/8.0f), &s, &c);
        g_TW16[t] = make_float2(c, -s);
    }
}

// ---------------- stage 1+2 fused: BARRIER-FREE per-warp 3-buf cp.async GEMM + radix-4x4 h-DFT ----------------
// smem floats: [0,8224) sB|sP   [8224,23584) sA(8w x 3buf x 640)|sG(8704)   [23584,24096) sTW   [24096,24128) s16
__global__ __launch_bounds__(256, 2) void fwd_fused_mma(const float* __restrict__ x) {
    extern __shared__ float s2[];
    float2* sB  = (float2*)s2;                   // GEMM phase
    float2* sP  = (float2*)s2;                   // [16][257] overlay (h-DFT phase)
    float*  sA  = s2 + 8224;                     // per-warp: 3 bufs x (32 rows x 20)
    float2* sG  = (float2*)(s2 + 8224);          // [256][17] float2 overlay (h-DFT phase)
    float2* sTW = (float2*)(s2 + 23584);         // 256
    float2* s16 = (float2*)(s2 + 24096);         // 16
    int bi = blockIdx.x, tid = threadIdx.x;
    int wid = tid >> 5, lane = tid & 31;
    int ln4 = lane >> 2, lc = lane & 3;

    const float2* gBt = (const float2*)g_B1;
    for (int i = tid; i < 4096; i += 256) sB[i] = gBt[i];
    sTW[tid & 255] = g_TW256[tid & 255];
    if (tid < 16) s16[tid] = g_TW16[tid];
    __syncthreads();    // sB visible before MMA consumption

    const float* xb = x + (size_t)bi * 65536;
    int r0 = wid * 32;
    float* sAw = sA + wid * 1920;
    uint32_t sAwb = smem_u32(sAw);

    // prologue: issue chunks 0..2
    #pragma unroll
    for (int cc = 0; cc < 3; cc++) {
        #pragma unroll
        for (int p = 0; p < 4; p++) {
            int s = p*32 + lane;
            int row = s >> 2, c4 = s & 3;
            CP_ASYNC16(sAwb + (uint32_t)((cc*640 + row*20 + c4*4)*4),
                       xb + (size_t)(r0 + row)*256 + cc*16 + c4*4);
        }
        CP_COMMIT();
    }

    float d[2][4][4] = {};
    #pragma unroll 1
    for (int c = 0; c < 16; c++) {
        if (c < 14) { CP_WAIT(2); } else if (c == 14) { CP_WAIT(1); } else { CP_WAIT(0); }
        const float* Ab = sAw + (c % 3)*640;
        #pragma unroll
        for (int kk = 0; kk < 2; kk++) {
            int kcl = kk*8;
            int gks = c*2 + kk;
            uint32_t a00 = __float_as_uint(tf32rna(Ab[(ln4     )*20 + kcl + lc    ]));
            uint32_t a01 = __float_as_uint(tf32rna(Ab[(ln4 +  8)*20 + kcl + lc    ]));
            uint32_t a02 = __float_as_uint(tf32rna(Ab[(ln4     )*20 + kcl + lc + 4]));
            uint32_t a03 = __float_as_uint(tf32rna(Ab[(ln4 +  8)*20 + kcl + lc + 4]));
            uint32_t a10 = __float_as_uint(tf32rna(Ab[(ln4 + 16)*20 + kcl + lc    ]));
            uint32_t a11 = __float_as_uint(tf32rna(Ab[(ln4 + 24)*20 + kcl + lc    ]));
            uint32_t a12 = __float_as_uint(tf32rna(Ab[(ln4 + 16)*20 + kcl + lc + 4]));
            uint32_t a13 = __float_as_uint(tf32rna(Ab[(ln4 + 24)*20 + kcl + lc + 4]));
            #pragma unroll
            for (int nt = 0; nt < 4; nt++) {
                float2 b = sB[(gks*32 + nt*8 + ln4)*4 + lc];
                uint32_t bx = __float_as_uint(b.x), by = __float_as_uint(b.y);
                mma_tf32(d[0][nt], a00, a01, a02, a03, bx, by);
                mma_tf32(d[1][nt], a10, a11, a12, a13, bx, by);
            }
        }
        if (c + 3 < 16) {
            #pragma unroll
            for (int p = 0; p < 4; p++) {
                int s = p*32 + lane;
                int row = s >> 2, c4 = s & 3;
                CP_ASYNC16(sAwb + (uint32_t)(((c % 3)*640 + row*20 + c4*4)*4),
                           xb + (size_t)(r0 + row)*256 + (c + 3)*16 + c4*4);
            }
            CP_COMMIT();
        }
    }
    __syncthreads();   // all warps done with sA region before sG overlays it

    #pragma unroll
    for (int gg = 0; gg < 2; gg++) {
        int rowl = r0 + gg*16 + ln4;
        #pragma unroll
        for (int nt = 0; nt < 4; nt++) {
            sG[rowl*17 + nt*4 + lc]       = make_float2(d[gg][nt][0], d[gg][nt][1]);
            sG[(rowl + 8)*17 + nt*4 + lc] = make_float2(d[gg][nt][2], d[gg][nt][3]);
        }
    }
    __syncthreads();

    // ---- h-DFT phase 1: 16-point DFT via radix-4 x radix-4 (sign -) ----
    int h0 = tid >> 4, ky = tid & 15;
    {
        float2 S[16];
        #pragma unroll
        for (int h1 = 0; h1 < 16; h1++) S[h1] = sG[(h1*16 + h0)*17 + ky];

        #pragma unroll
        for (int h1b = 0; h1b < 4; h1b++) {
            float2 g0 = S[h1b], g1 = S[h1b+4], g2 = S[h1b+8], g3 = S[h1b+12];
            float2 e0 = cadd(g0, g2), e1 = csub(g0, g2);
            float2 o0 = cadd(g1, g3), o1 = csub(g1, g3);
            float2 R0 = cadd(e0, o0);
            float2 R1 = subi(e1, o1);
            float2 R2 = csub(e0, o0);
            float2 R3 = addi(e1, o1);
            S[h1b]      = R0;
            S[h1b + 4]  = (h1b == 0) ? R1 : cmul(R1, s16[h1b]);
            S[h1b + 8]  = (h1b == 0) ? R2 : cmul(R2, s16[(2*h1b) & 15]);
            S[h1b + 12] = (h1b == 0) ? R3 : cmul(R3, s16[(3*h1b) & 15]);
        }
        #pragma unroll
        for (int m = 0; m < 4; m++) {
            float2 s0 = S[0 + 4*m], s1 = S[1 + 4*m], s2 = S[2 + 4*m], s3 = S[3 + 4*m];
            float2 E0 = cadd(s0, s2), E1 = csub(s0, s2);
            float2 O0 = cadd(s1, s3), O1 = csub(s1, s3);
            sP[h0*257 + (m     )*16 + ky] = cadd(E0, O0);
            sP[h0*257 + (m +  4)*16 + ky] = subi(E1, O1);
            sP[h0*257 + (m +  8)*16 + ky] = csub(E0, O0);
            sP[h0*257 + (m + 12)*16 + ky] = addi(E1, O1);
        }
    }
    __syncthreads();

    // ---- h-DFT phase 2: combine + twiddle; write mode-major g_Xft ----
    int a = h0;
    float2 x1 = make_float2(0.f, 0.f), x2 = make_float2(0.f, 0.f);
    #pragma unroll
    for (int hh = 0; hh < 16; hh++) {
        float2 p  = sP[hh*257 + a*16 + ky];
        float2 t1 = sTW[a*16 + hh];
        float2 q  = cmul(p, t1);
        x1 = cadd(x1, q);
        float2 c = s16[hh];
        x2 = cadd(x2, cmulc(q, c));
    }
    g_Xft[(a*16 + ky)*512 + bi]        = x1;
    g_Xft[((16 + a)*16 + ky)*512 + bi] = x2;
}

// ---------------- stage 3: channel mix (contiguous X reads) ----------------
__global__ __launch_bounds__(256) void chan_mix() {
    __shared__ float2 sW[32*32];
    __shared__ float2 sX[16*32];
    int mode  = blockIdx.x;
    int kxidx = mode >> 4, ky = mode & 15;
    int tid   = threadIdx.x;

    #pragma unroll
    for (int p = 0; p < 4; p++) sW[tid + p*256] = g_wpack[mode*1024 + tid + p*256];
    sX[tid]       = g_Xft[mode*512 + tid];
    sX[tid + 256] = g_Xft[mode*512 + tid + 256];
    __syncthreads();

    int o = tid & 31, b0 = tid >> 5;
    float2 acc0 = make_float2(0.f, 0.f), acc1 = make_float2(0.f, 0.f);
    #pragma unroll
    for (int i = 0; i < 32; i++) {
        float2 wv = sW[i*32 + o];
        float2 x0 = sX[b0*32 + i];
        float2 x1 = sX[(b0 + 8)*32 + i];
        acc0.x += x0.x*wv.x - x0.y*wv.y; acc0.y += x0.x*wv.y + x0.y*wv.x;
        acc1.x += x1.x*wv.x - x1.y*wv.y; acc1.y += x1.x*wv.y + x1.y*wv.x;
    }
    g_Yft[((b0*32 + o)*32 + kxidx)*16 + ky]       = acc0;
    g_Yft[(((b0 + 8)*32 + o)*32 + kxidx)*16 + ky] = acc1;
}

// ---------------- stage 4+5 fused, M-split; shuffle-transposed coalesced epilogue ----------------
__global__ __launch_bounds__(256, 3) void inv_fused_mma(float* __restrict__ out) {
    extern __shared__ float s5[];
    float*  sZ  = s5;                          // [128][36] floats = 18432 B
    float2* sB  = (float2*)(s5 + 4608);        // 4096 float2 = 32768 B
    float2* sY  = sB + 4096;                   // 512
    float2* sTW = sY + 512;                    // 256
    float2* s16 = sTW + 256;                   // 16
    int bo = blockIdx.x >> 1, mh = blockIdx.x & 1;
    int tid = threadIdx.x;
    int wid = tid >> 5, lane = tid & 31;
    int ln4 = lane >> 2, lc = lane & 3;

    const float2* gBt = (const float2*)g_B5;
    #pragma unroll
    for (int p = 0; p < 16; p++) sB[tid + p*256] = gBt[tid + p*256];
    sY[tid]       = g_Yft[bo*512 + tid];
    sY[tid + 256] = g_Yft[bo*512 + tid + 256];
    sTW[tid & 255] = g_TW256[tid & 255];
    if (tid < 16) s16[tid] = g_TW16[tid];
    __syncthreads();

    // ---- phase A: inverse h-DFT (sign +) for h1 in [mh*8, mh*8+8) ----
    int h0 = tid >> 4, ky = tid & 15;
    {
        float2 w16 = s16[h0];
        float2 Q[16];
        #pragma unroll
        for (int j = 0; j < 16; j++) {
            float2 t = sTW[j*16 + h0];
            float2 u = make_float2(t.x, -t.y);
            float2 v = cmul(u, w16);
            float2 y1 = sY[j*16 + ky], y2 = sY[(16 + j)*16 + ky];
            Q[j] = cadd(cmul(y1, u), cmul(y2, v));
        }
        #pragma unroll
        for (int jb = 0; jb < 4; jb++) {
            float2 q0 = Q[jb], q1 = Q[jb+4], q2 = Q[jb+8], q3 = Q[jb+12];
            float2 e0 = cadd(q0, q2), e1 = csub(q0, q2);
            float2 o0 = cadd(q1, q3), o1 = csub(q1, q3);
            float2 R0 = cadd(e0, o0);
            float2 R1 = addi(e1, o1);
            float2 R2 = csub(e0, o0);
            float2 R3 = subi(e1, o1);
            Q[jb]      = R0;
            Q[jb + 4]  = (jb == 0) ? R1 : cmulc(R1, s16[jb]);
            Q[jb + 8]  = (jb == 0) ? R2 : cmulc(R2, s16[(2*jb) & 15]);
            Q[jb + 12] = (jb == 0) ? R3 : cmulc(R3, s16[(3*jb) & 15]);
        }
        #pragma unroll
        for (int m = 0; m < 4; m++) {
            float2 s0 = Q[0 + 4*m], s1 = Q[1 + 4*m], s2 = Q[2 + 4*m], s3 = Q[3 + 4*m];
            float2 Epl = cadd(s0, s2), Emn = csub(s0, s2);
            float2 Opl = cadd(s1, s3), Omn = csub(s1, s3);
            float2 accE, accO;
            if (mh == 0) { accE = cadd(Epl, Opl); accO = addi(Emn, Omn); }
            else         { accE = csub(Epl, Opl); accO = subi(Emn, Omn); }
            int rE = (m    )*16 + h0;
            int rO = (m + 4)*16 + h0;
            *(float2*)&sZ[rE*36 + 2*ky] = make_float2(tf32rna(accE.x), tf32rna(accE.y));
            *(float2*)&sZ[rO*36 + 2*ky] = make_float2(tf32rna(accO.x), tf32rna(accO.y));
        }
    }
    __syncthreads();

    // ---- phase B: M=128 local rows, N=256; warp-tile 32x32; A frags hoisted across nh ----
    int warpM2 = wid >> 2, warpN = wid & 3;
    size_t obase = (size_t)bo*256 + mh*128;
    #pragma unroll 1
    for (int mt = 0; mt < 2; mt++) {
        int rbase = mt*64 + warpM2*32;
        float fa[4][8];
        #pragma unroll
        for (int ks = 0; ks < 4; ks++) {
            int kc = ks*8;
            fa[ks][0] = sZ[(rbase + ln4     )*36 + kc + lc    ];
            fa[ks][1] = sZ[(rbase + ln4 +  8)*36 + kc + lc    ];
            fa[ks][2] = sZ[(rbase + ln4     )*36 + kc + lc + 4];
            fa[ks][3] = sZ[(rbase + ln4 +  8)*36 + kc + lc + 4];
            fa[ks][4] = sZ[(rbase + ln4 + 16)*36 + kc + lc    ];
            fa[ks][5] = sZ[(rbase + ln4 + 24)*36 + kc + lc    ];
            fa[ks][6] = sZ[(rbase + ln4 + 16)*36 + kc + lc + 4];
            fa[ks][7] = sZ[(rbase + ln4 + 24)*36 + kc + lc + 4];
        }
        #pragma unroll 1
        for (int nh = 0; nh < 2; nh++) {
            int ncol0 = nh*128 + warpN*32;
            float d[2][4][4] = {};
            #pragma unroll
            for (int ks = 0; ks < 4; ks++) {
                uint32_t a00 = __float_as_uint(fa[ks][0]), a01 = __float_as_uint(fa[ks][1]);
                uint32_t a02 = __float_as_uint(fa[ks][2]), a03 = __float_as_uint(fa[ks][3]);
                uint32_t a10 = __float_as_uint(fa[ks][4]), a11 = __float_as_uint(fa[ks][5]);
                uint32_t a12 = __float_as_uint(fa[ks][6]), a13 = __float_as_uint(fa[ks][7]);
                #pragma unroll
                for (int nt = 0; nt < 4; nt++) {
                    float2 b = sB[(ks*256 + ncol0 + nt*8 + ln4)*4 + lc];
                    uint32_t bx = __float_as_uint(b.x), by = __float_as_uint(b.y);
                    mma_tf32(d[0][nt], a00, a01, a02, a03, bx, by);
                    mma_tf32(d[1][nt], a10, a11, a12, a13, bx, by);
                }
            }
            // coalesced epilogue: quad transpose -> each lane stores 8 consecutive cols per row
            #pragma unroll
            for (int gg = 0; gg < 2; gg++) {
                float2 p[4], q[4];
                #pragma unroll
                for (int nt = 0; nt < 4; nt++) {
                    p[nt] = make_float2(d[gg][nt][0], d[gg][nt][1]);   // row r
                    q[nt] = make_float2(d[gg][nt][2], d[gg][nt][3]);   // row r+8
                }
                quad_transpose(p, lc);
                quad_transpose(q, lc);
                size_t rowg = obase + rbase + gg*16 + ln4;
                float* o0 = out + rowg*256 + ncol0 + 8*lc;
                float* o1 = out + (rowg + 8)*256 + ncol0 + 8*lc;
                *(float4*)&o0[0] = make_float4(p[0].x, p[0].y, p[1].x, p[1].y);
                *(float4*)&o0[4] = make_float4(p[2].x, p[2].y, p[3].x, p[3].y);
                *(float4*)&o1[0] = make_float4(q[0].x, q[0].y, q[1].x, q[1].y);
                *(float4*)&o1[4] = make_float4(q[2].x, q[2].y, q[3].x, q[3].y);
            }
        }
    }
}

// ---------------- launch ----------------
extern "C" void kernel_launch(void* const* d_in, const int* in_sizes, int n_in,
                              void* d_out, int out_size) {
    const float* x   = (const float*)d_in[0];
    const float* w1r = (const float*)d_in[1];
    const float* w1i = (const float*)d_in[2];
    const float* w2r = (const float*)d_in[3];
    const float* w2i = (const float*)d_in[4];
    float* out = (float*)d_out;

    const int FW_SMEM = 24128 * 4;                                // 96512 -> 2 CTAs/SM, depth-3
    const int IV_SMEM = (4608 + 8192 + 1024 + 512 + 32) * 4;      // 57472
    cudaFuncSetAttribute(fwd_fused_mma, cudaFuncAttributeMaxDynamicSharedMemorySize, FW_SMEM);
    cudaFuncSetAttribute(inv_fused_mma, cudaFuncAttributeMaxDynamicSharedMemorySize, IV_SMEM);

    prep<<<162, 256>>>(w1r, w1i, w2r, w2i);
    fwd_fused_mma<<<BB*CIN, 256, FW_SMEM>>>(x);
    chan_mix<<<512, 256>>>();
    inv_fused_mma<<<BB*COUT*2, 256, IV_SMEM>>>(out);
}

// round 17
// speedup vs baseline: 1.0495x; 1.0495x over previous
#include <cuda_runtime.h>
#include <cstdint>

#define BB   16
#define CIN  32
#define COUT 32
#define HH   256
#define WW   256

// ---------------- scratch (device globals; no cudaMalloc) ----------------
__device__ float2 g_B1[32*32*4];                     // stage1 B frag pairs [kstep32][n32][c4]
__device__ float2 g_B5[4*256*4];                     // stage5 B frag pairs [kstep4][w256][c4]
__device__ float2 g_TW256[256];                      // e^{-2pi i a h0/256}, [a*16+h0]
__device__ float2 g_TW16[16];                        // e^{-2pi i t/16}
__device__ float2 g_wpack[512*32*32];                // [mode][i*32+o]
__device__ float2 g_Xft[512*512];                    // [mode][b*32+i]  (mode-major)
__device__ float2 g_Yft[BB*COUT*32*16];              // [b,o][kxidx][ky]

__device__ __forceinline__ float tf32rna(float x) {
    uint32_t u; asm("cvt.rna.tf32.f32 %0, %1;" : "=r"(u) : "f"(x));
    return __uint_as_float(u);
}
__device__ __forceinline__ uint32_t smem_u32(const void* p) {
    uint32_t a;
    asm("{ .reg .u64 t; cvta.to.shared.u64 t, %1; cvt.u32.u64 %0, t; }" : "=r"(a) : "l"(p));
    return a;
}
__device__ __forceinline__ float2 cadd(float2 a, float2 b) { return make_float2(a.x+b.x, a.y+b.y); }
__device__ __forceinline__ float2 csub(float2 a, float2 b) { return make_float2(a.x-b.x, a.y-b.y); }
__device__ __forceinline__ float2 cmul(float2 a, float2 b) {        // a*b
    return make_float2(a.x*b.x - a.y*b.y, a.x*b.y + a.y*b.x);
}
__device__ __forceinline__ float2 cmulc(float2 a, float2 b) {       // a*conj(b)
    return make_float2(a.x*b.x + a.y*b.y, a.y*b.x - a.x*b.y);
}
__device__ __forceinline__ float2 addi(float2 a, float2 b) { return make_float2(a.x - b.y, a.y + b.x); }  // a + i*b
__device__ __forceinline__ float2 subi(float2 a, float2 b) { return make_float2(a.x + b.y, a.y - b.x); }  // a - i*b

#define CP_ASYNC16(dst, src) asm volatile("cp.async.cg.shared.global [%0], [%1], 16;" :: "r"(dst), "l"(src))
#define CP_COMMIT()          asm volatile("cp.async.commit_group;" ::: "memory")
#define CP_WAIT(n)           asm volatile("cp.async.wait_group %0;" :: "n"(n) : "memory")

__device__ __forceinline__ void mma_tf32(float d[4], uint32_t a0, uint32_t a1, uint32_t a2, uint32_t a3,
                                         uint32_t b0, uint32_t b1) {
    asm volatile(
        "mma.sync.aligned.m16n8k8.row.col.f32.tf32.tf32.f32 "
        "{%0,%1,%2,%3}, {%4,%5,%6,%7}, {%8,%9}, {%0,%1,%2,%3};"
        : "+f"(d[0]), "+f"(d[1]), "+f"(d[2]), "+f"(d[3])
        : "r"(a0), "r"(a1), "r"(a2), "r"(a3), "r"(b0), "r"(b1));
}

// ---------------- prep: blocks 0..127 repack (smem transpose), 128..161 tables ----------------
__global__ void prep(const float* __restrict__ w1r, const float* __restrict__ w1i,
                     const float* __restrict__ w2r, const float* __restrict__ w2i) {
    __shared__ float sw[4][2048];    // 8 pairs x 256 modes, 4 arrays (32 KB)
    int blk = blockIdx.x, tid = threadIdx.x;
    if (blk < 128) {
        int p0 = blk * 8;
        const float* srcs[4] = {w1r, w1i, w2r, w2i};
        #pragma unroll
        for (int a = 0; a < 4; a++) {
            const float4* s4 = (const float4*)(srcs[a] + p0*256);
            float4* d4 = (float4*)sw[a];
            d4[tid]       = s4[tid];
            d4[tid + 256] = s4[tid + 256];
        }
        __syncthreads();
        int j = tid;
        float2 v1[8], v2[8];
        #pragma unroll
        for (int pl = 0; pl < 8; pl++) {
            v1[pl] = make_float2(sw[0][pl*256 + j], sw[1][pl*256 + j]);
            v2[pl] = make_float2(sw[2][pl*256 + j], sw[3][pl*256 + j]);
        }
        float4* o1 = (float4*)&g_wpack[(size_t)j*1024 + p0];
        float4* o2 = (float4*)&g_wpack[(size_t)(256 + j)*1024 + p0];
        #pragma unroll
        for (int q = 0; q < 4; q++) {
            o1[q] = make_float4(v1[2*q].x, v1[2*q].y, v1[2*q+1].x, v1[2*q+1].y);
            o2[q] = make_float4(v2[2*q].x, v2[2*q].y, v2[2*q+1].x, v2[2*q+1].y);
        }
        return;
    }
    int idx = (blk - 128) * 256 + tid;
    if (idx < 4096) {                        // g_B1[kstep][n][c]
        int c = idx & 3, n = (idx >> 2) & 31, kstep = idx >> 7;
        int ky = n >> 1;
        int k0 = kstep*8 + c, k1 = k0 + 4;
        int t0 = (ky * k0) & 255, t1 = (ky * k1) & 255;
        float s0, c0, s1, c1;
        sincospif(t0 * (1.0f/128.0f), &s0, &c0);
        sincospif(t1 * (1.0f/128.0f), &s1, &c1);
        float v0 = (n & 1) ? -s0 : c0;
        float v1 = (n & 1) ? -s1 : c1;
        g_B1[idx] = make_float2(tf32rna(v0), tf32rna(v1));
    } else if (idx < 8192) {                 // g_B5[kstep][w][c]
        int j = idx - 4096;
        int c = j & 3, w = (j >> 2) & 255, kstep = j >> 10;
        int k0 = kstep*8 + c, k1 = k0 + 4;
        int ky0 = k0 >> 1, ky1 = k1 >> 1;
        int t0 = (ky0 * w) & 255, t1 = (ky1 * w) & 255;
        float s0, c0, s1, c1;
        sincospif(t0 * (1.0f/128.0f), &s0, &c0);
        sincospif(t1 * (1.0f/128.0f), &s1, &c1);
        float cf0 = ((ky0 == 0) ? 1.0f : 2.0f) * (1.0f/65536.0f);
        float cf1 = ((ky1 == 0) ? 1.0f : 2.0f) * (1.0f/65536.0f);
        float v0 = (k0 & 1) ? -cf0 * s0 : cf0 * c0;
        float v1 = (k1 & 1) ? -cf1 * s1 : cf1 * c1;
        g_B5[j] = make_float2(tf32rna(v0), tf32rna(v1));
    } else if (idx < 8448) {                 // g_TW256[a*16+h0]
        int j = idx - 8192;
        int a = j >> 4, h0 = j & 15;
        int t = (a * h0) & 255;
        float s, c; sincospif(t * (1.0f/128.0f), &s, &c);
        g_TW256[j] = make_float2(c, -s);
    } else if (idx < 8464) {                 // g_TW16[t]
        int t = idx - 8448;
        float s, c; sincospif(t * (1.0f/8.0f), &s, &c);
        g_TW16[t] = make_float2(c, -s);
    }
}

// ---------------- stage 1+2 fused: BARRIER-FREE per-warp 4-buf cp.async GEMM + radix-4x4 h-DFT ----------------
// smem floats: [0,8224) sB|sP   [8224,28704) sA(8w x 4buf x 640)|sG(8704)   [28704,28736) s16
__global__ __launch_bounds__(256, 2) void fwd_fused_mma(const float* __restrict__ x) {
    extern __shared__ float s2[];
    float2* sB  = (float2*)s2;                   // GEMM phase
    float2* sP  = (float2*)s2;                   // [16][257] overlay (h-DFT phase)
    float*  sA  = s2 + 8224;                     // per-warp: 4 bufs x (32 rows x 20)
    float2* sG  = (float2*)(s2 + 8224);          // [256][17] float2 overlay (h-DFT phase)
    float2* s16 = (float2*)(s2 + 28704);         // 16
    int bi = blockIdx.x, tid = threadIdx.x;
    int wid = tid >> 5, lane = tid & 31;
    int ln4 = lane >> 2, lc = lane & 3;

    const float2* gBt = (const float2*)g_B1;
    for (int i = tid; i < 4096; i += 256) sB[i] = gBt[i];
    if (tid < 16) s16[tid] = g_TW16[tid];
    __syncthreads();    // sB visible before MMA consumption

    const float* xb = x + (size_t)bi * 65536;
    int r0 = wid * 32;
    float* sAw = sA + wid * 2560;
    uint32_t sAwb = smem_u32(sAw);

    // prologue: issue chunks 0..3 into buffers 0..3
    #pragma unroll
    for (int cc = 0; cc < 4; cc++) {
        #pragma unroll
        for (int p = 0; p < 4; p++) {
            int s = p*32 + lane;
            int row = s >> 2, c4 = s & 3;
            CP_ASYNC16(sAwb + (uint32_t)((cc*640 + row*20 + c4*4)*4),
                       xb + (size_t)(r0 + row)*256 + cc*16 + c4*4);
        }
        CP_COMMIT();
    }

    float d[2][4][4] = {};
    #pragma unroll 1
    for (int c = 0; c < 16; c++) {
        if (c < 13)      { CP_WAIT(3); }
        else if (c == 13){ CP_WAIT(2); }
        else if (c == 14){ CP_WAIT(1); }
        else             { CP_WAIT(0); }
        const float* Ab = sAw + (c & 3)*640;
        #pragma unroll
        for (int kk = 0; kk < 2; kk++) {
            int kcl = kk*8;
            int gks = c*2 + kk;
            uint32_t a00 = __float_as_uint(tf32rna(Ab[(ln4     )*20 + kcl + lc    ]));
            uint32_t a01 = __float_as_uint(tf32rna(Ab[(ln4 +  8)*20 + kcl + lc    ]));
            uint32_t a02 = __float_as_uint(tf32rna(Ab[(ln4     )*20 + kcl + lc + 4]));
            uint32_t a03 = __float_as_uint(tf32rna(Ab[(ln4 +  8)*20 + kcl + lc + 4]));
            uint32_t a10 = __float_as_uint(tf32rna(Ab[(ln4 + 16)*20 + kcl + lc    ]));
            uint32_t a11 = __float_as_uint(tf32rna(Ab[(ln4 + 24)*20 + kcl + lc    ]));
            uint32_t a12 = __float_as_uint(tf32rna(Ab[(ln4 + 16)*20 + kcl + lc + 4]));
            uint32_t a13 = __float_as_uint(tf32rna(Ab[(ln4 + 24)*20 + kcl + lc + 4]));
            #pragma unroll
            for (int nt = 0; nt < 4; nt++) {
                float2 b = sB[(gks*32 + nt*8 + ln4)*4 + lc];
                uint32_t bx = __float_as_uint(b.x), by = __float_as_uint(b.y);
                mma_tf32(d[0][nt], a00, a01, a02, a03, bx, by);
                mma_tf32(d[1][nt], a10, a11, a12, a13, bx, by);
            }
        }
        // refill buffer just consumed (MMA scoreboard dep orders the reads before these writes)
        if (c + 4 < 16) {
            #pragma unroll
            for (int p = 0; p < 4; p++) {
                int s = p*32 + lane;
                int row = s >> 2, c4 = s & 3;
                CP_ASYNC16(sAwb + (uint32_t)(((c & 3)*640 + row*20 + c4*4)*4),
                           xb + (size_t)(r0 + row)*256 + (c + 4)*16 + c4*4);
            }
            CP_COMMIT();
        }
    }
    __syncthreads();   // all warps done with sA region before sG overlays it

    #pragma unroll
    for (int gg = 0; gg < 2; gg++) {
        int rowl = r0 + gg*16 + ln4;
        #pragma unroll
        for (int nt = 0; nt < 4; nt++) {
            sG[rowl*17 + nt*4 + lc]       = make_float2(d[gg][nt][0], d[gg][nt][1]);
            sG[(rowl + 8)*17 + nt*4 + lc] = make_float2(d[gg][nt][2], d[gg][nt][3]);
        }
    }
    __syncthreads();

    // ---- h-DFT phase 1: 16-point DFT via radix-4 x radix-4 (sign -) ----
    int h0 = tid >> 4, ky = tid & 15;
    {
        float2 S[16];
        #pragma unroll
        for (int h1 = 0; h1 < 16; h1++) S[h1] = sG[(h1*16 + h0)*17 + ky];

        #pragma unroll
        for (int h1b = 0; h1b < 4; h1b++) {
            float2 g0 = S[h1b], g1 = S[h1b+4], g2 = S[h1b+8], g3 = S[h1b+12];
            float2 e0 = cadd(g0, g2), e1 = csub(g0, g2);
            float2 o0 = cadd(g1, g3), o1 = csub(g1, g3);
            float2 R0 = cadd(e0, o0);
            float2 R1 = subi(e1, o1);
            float2 R2 = csub(e0, o0);
            float2 R3 = addi(e1, o1);
            S[h1b]      = R0;
            S[h1b + 4]  = (h1b == 0) ? R1 : cmul(R1, s16[h1b]);
            S[h1b + 8]  = (h1b == 0) ? R2 : cmul(R2, s16[(2*h1b) & 15]);
            S[h1b + 12] = (h1b == 0) ? R3 : cmul(R3, s16[(3*h1b) & 15]);
        }
        #pragma unroll
        for (int m = 0; m < 4; m++) {
            float2 s0 = S[0 + 4*m], s1 = S[1 + 4*m], s2 = S[2 + 4*m], s3 = S[3 + 4*m];
            float2 E0 = cadd(s0, s2), E1 = csub(s0, s2);
            float2 O0 = cadd(s1, s3), O1 = csub(s1, s3);
            sP[h0*257 + (m     )*16 + ky] = cadd(E0, O0);
            sP[h0*257 + (m +  4)*16 + ky] = subi(E1, O1);
            sP[h0*257 + (m +  8)*16 + ky] = csub(E0, O0);
            sP[h0*257 + (m + 12)*16 + ky] = addi(E1, O1);
        }
    }
    __syncthreads();

    // ---- h-DFT phase 2: combine + twiddle (recurrence, no table); write mode-major g_Xft ----
    int a = h0;
    float2 x1 = make_float2(0.f, 0.f), x2 = make_float2(0.f, 0.f);
    float sa, ca;
    sincospif(a * (1.0f/128.0f), &sa, &ca);
    float2 step = make_float2(ca, -sa);      // e^{-2pi i a/256}
    float2 t1 = make_float2(1.f, 0.f);
    #pragma unroll
    for (int hh = 0; hh < 16; hh++) {
        float2 p = sP[hh*257 + a*16 + ky];
        float2 q = cmul(p, t1);
        x1 = cadd(x1, q);
        float2 c = s16[hh];
        x2 = cadd(x2, cmulc(q, c));
        t1 = cmul(t1, step);
    }
    g_Xft[(a*16 + ky)*512 + bi]        = x1;
    g_Xft[((16 + a)*16 + ky)*512 + bi] = x2;
}

// ---------------- stage 3: channel mix (contiguous X reads) ----------------
__global__ __launch_bounds__(256) void chan_mix() {
    __shared__ float2 sW[32*32];
    __shared__ float2 sX[16*32];
    int mode  = blockIdx.x;
    int kxidx = mode >> 4, ky = mode & 15;
    int tid   = threadIdx.x;

    #pragma unroll
    for (int p = 0; p < 4; p++) sW[tid + p*256] = g_wpack[mode*1024 + tid + p*256];
    sX[tid]       = g_Xft[mode*512 + tid];
    sX[tid + 256] = g_Xft[mode*512 + tid + 256];
    __syncthreads();

    int o = tid & 31, b0 = tid >> 5;
    float2 acc0 = make_float2(0.f, 0.f), acc1 = make_float2(0.f, 0.f);
    #pragma unroll
    for (int i = 0; i < 32; i++) {
        float2 wv = sW[i*32 + o];
        float2 x0 = sX[b0*32 + i];
        float2 x1 = sX[(b0 + 8)*32 + i];
        acc0.x += x0.x*wv.x - x0.y*wv.y; acc0.y += x0.x*wv.y + x0.y*wv.x;
        acc1.x += x1.x*wv.x - x1.y*wv.y; acc1.y += x1.x*wv.y + x1.y*wv.x;
    }
    g_Yft[((b0*32 + o)*32 + kxidx)*16 + ky]       = acc0;
    g_Yft[(((b0 + 8)*32 + o)*32 + kxidx)*16 + ky] = acc1;
}

// ---------------- stage 4+5 fused, M-split; phase-A h1-DFT via radix-4 x radix-4 ----------------
__global__ __launch_bounds__(256, 3) void inv_fused_mma(float* __restrict__ out) {
    extern __shared__ float s5[];
    float*  sZ  = s5;                          // [128][36] floats = 18432 B
    float2* sB  = (float2*)(s5 + 4608);        // 4096 float2 = 32768 B
    float2* sY  = sB + 4096;                   // 512
    float2* sTW = sY + 512;                    // 256
    float2* s16 = sTW + 256;                   // 16
    int bo = blockIdx.x >> 1, mh = blockIdx.x & 1;
    int tid = threadIdx.x;
    int wid = tid >> 5, lane = tid & 31;
    int ln4 = lane >> 2, lc = lane & 3;

    const float2* gBt = (const float2*)g_B5;
    #pragma unroll
    for (int p = 0; p < 16; p++) sB[tid + p*256] = gBt[tid + p*256];
    sY[tid]       = g_Yft[bo*512 + tid];
    sY[tid + 256] = g_Yft[bo*512 + tid + 256];
    sTW[tid & 255] = g_TW256[tid & 255];
    if (tid < 16) s16[tid] = g_TW16[tid];
    __syncthreads();

    // ---- phase A: inverse h-DFT (sign +) for h1 in [mh*8, mh*8+8) ----
    int h0 = tid >> 4, ky = tid & 15;
    {
        float2 w16 = s16[h0];
        float2 Q[16];
        #pragma unroll
        for (int j = 0; j < 16; j++) {
            float2 t = sTW[j*16 + h0];
            float2 u = make_float2(t.x, -t.y);
            float2 v = cmul(u, w16);
            float2 y1 = sY[j*16 + ky], y2 = sY[(16 + j)*16 + ky];
            Q[j] = cadd(cmul(y1, u), cmul(y2, v));
        }
        #pragma unroll
        for (int jb = 0; jb < 4; jb++) {
            float2 q0 = Q[jb], q1 = Q[jb+4], q2 = Q[jb+8], q3 = Q[jb+12];
            float2 e0 = cadd(q0, q2), e1 = csub(q0, q2);
            float2 o0 = cadd(q1, q3), o1 = csub(q1, q3);
            float2 R0 = cadd(e0, o0);
            float2 R1 = addi(e1, o1);
            float2 R2 = csub(e0, o0);
            float2 R3 = subi(e1, o1);
            Q[jb]      = R0;
            Q[jb + 4]  = (jb == 0) ? R1 : cmulc(R1, s16[jb]);
            Q[jb + 8]  = (jb == 0) ? R2 : cmulc(R2, s16[(2*jb) & 15]);
            Q[jb + 12] = (jb == 0) ? R3 : cmulc(R3, s16[(3*jb) & 15]);
        }
        #pragma unroll
        for (int m = 0; m < 4; m++) {
            float2 s0 = Q[0 + 4*m], s1 = Q[1 + 4*m], s2 = Q[2 + 4*m], s3 = Q[3 + 4*m];
            float2 Epl = cadd(s0, s2), Emn = csub(s0, s2);
            float2 Opl = cadd(s1, s3), Omn = csub(s1, s3);
            float2 accE, accO;
            if (mh == 0) { accE = cadd(Epl, Opl); accO = addi(Emn, Omn); }
            else         { accE = csub(Epl, Opl); accO = subi(Emn, Omn); }
            int rE = (m    )*16 + h0;
            int rO = (m + 4)*16 + h0;
            *(float2*)&sZ[rE*36 + 2*ky] = make_float2(tf32rna(accE.x), tf32rna(accE.y));
            *(float2*)&sZ[rO*36 + 2*ky] = make_float2(tf32rna(accO.x), tf32rna(accO.y));
        }
    }
    __syncthreads();

    // ---- phase B: M=128 local rows, N=256; warp-tile 32x32; A frags hoisted across nh ----
    int warpM2 = wid >> 2, warpN = wid & 3;
    size_t obase = (size_t)bo*256 + mh*128;
    #pragma unroll 1
    for (int mt = 0; mt < 2; mt++) {
        int rbase = mt*64 + warpM2*32;
        float fa[4][8];
        #pragma unroll
        for (int ks = 0; ks < 4; ks++) {
            int kc = ks*8;
            fa[ks][0] = sZ[(rbase + ln4     )*36 + kc + lc    ];
            fa[ks][1] = sZ[(rbase + ln4 +  8)*36 + kc + lc    ];
            fa[ks][2] = sZ[(rbase + ln4     )*36 + kc + lc + 4];
            fa[ks][3] = sZ[(rbase + ln4 +  8)*36 + kc + lc + 4];
            fa[ks][4] = sZ[(rbase + ln4 + 16)*36 + kc + lc    ];
            fa[ks][5] = sZ[(rbase + ln4 + 24)*36 + kc + lc    ];
            fa[ks][6] = sZ[(rbase + ln4 + 16)*36 + kc + lc + 4];
            fa[ks][7] = sZ[(rbase + ln4 + 24)*36 + kc + lc + 4];
        }
        #pragma unroll 1
        for (int nh = 0; nh < 2; nh++) {
            int ncol0 = nh*128 + warpN*32;
            float d[2][4][4] = {};
            #pragma unroll
            for (int ks = 0; ks < 4; ks++) {
                uint32_t a00 = __float_as_uint(fa[ks][0]), a01 = __float_as_uint(fa[ks][1]);
                uint32_t a02 = __float_as_uint(fa[ks][2]), a03 = __float_as_uint(fa[ks][3]);
                uint32_t a10 = __float_as_uint(fa[ks][4]), a11 = __float_as_uint(fa[ks][5]);
                uint32_t a12 = __float_as_uint(fa[ks][6]), a13 = __float_as_uint(fa[ks][7]);
                #pragma unroll
                for (int nt = 0; nt < 4; nt++) {
                    float2 b = sB[(ks*256 + ncol0 + nt*8 + ln4)*4 + lc];
                    uint32_t bx = __float_as_uint(b.x), by = __float_as_uint(b.y);
                    mma_tf32(d[0][nt], a00, a01, a02, a03, bx, by);
                    mma_tf32(d[1][nt], a10, a11, a12, a13, bx, by);
                }
            }
            #pragma unroll
            for (int gg = 0; gg < 2; gg++) {
                size_t rowg = obase + rbase + gg*16 + ln4;
                float* o0 = out + rowg*256;
                float* o1 = out + (rowg + 8)*256;
                #pragma unroll
                for (int nt = 0; nt < 4; nt++) {
                    int col = ncol0 + nt*8 + 2*lc;
                    __stcs((float2*)&o0[col], make_float2(d[gg][nt][0], d[gg][nt][1]));
                    __stcs((float2*)&o1[col], make_float2(d[gg][nt][2], d[gg][nt][3]));
                }
            }
        }
    }
}

// ---------------- launch ----------------
extern "C" void kernel_launch(void* const* d_in, const int* in_sizes, int n_in,
                              void* d_out, int out_size) {
    const float* x   = (const float*)d_in[0];
    const float* w1r = (const float*)d_in[1];
    const float* w1i = (const float*)d_in[2];
    const float* w2r = (const float*)d_in[3];
    const float* w2i = (const float*)d_in[4];
    float* out = (float*)d_out;

    const int FW_SMEM = 28736 * 4;                                // 114944 -> 2 CTAs/SM, depth-4
    const int IV_SMEM = (4608 + 8192 + 1024 + 512 + 32) * 4;      // 57472
    cudaFuncSetAttribute(fwd_fused_mma, cudaFuncAttributeMaxDynamicSharedMemorySize, FW_SMEM);
    cudaFuncSetAttribute(inv_fused_mma, cudaFuncAttributeMaxDynamicSharedMemorySize, IV_SMEM);

    prep<<<162, 256>>>(w1r, w1i, w2r, w2i);
    fwd_fused_mma<<<BB*CIN, 256, FW_SMEM>>>(x);
    chan_mix<<<512, 256>>>();
    inv_fused_mma<<<BB*COUT*2, 256, IV_SMEM>>>(out);
}